// round 7
// baseline (speedup 1.0000x reference)
#include <cuda_runtime.h>
#include <cuda_bf16.h>

#define NA 8
#define BB 32
#define NB 256
#define FF 256
#define TT 64
#define HH 8
#define DD 32
#define SCALE 0.0625f

typedef unsigned int u32;

// ---- packed (bf16 hi | bf16 lo<<16) intermediates ----
__device__ u32 g_w [3*FF*FF];      // [mat][fout=h*32+d][f]
__device__ u32 g_wp[FF*FF];        // [g][f]
__device__ u32 g_q [HH*NB*TT*DD];  // [h][nb][t][d]  (pre-scaled)
__device__ u32 g_k [HH*NB*TT*DD];  // [h][nb][s][d]
__device__ u32 g_v [HH*NB*DD*TT];  // [h][nb][d][s]
__device__ u32 g_y [NB*TT*FF];     // [nb][t][f]

__device__ __forceinline__ u32 splitpack(float x) {
    __nv_bfloat16 h = __float2bfloat16(x);
    __nv_bfloat16 l = __float2bfloat16(x - __bfloat162float(h));
    return (u32)__bfloat16_as_ushort(h) | ((u32)__bfloat16_as_ushort(l) << 16);
}
__device__ __forceinline__ u32 hi2(u32 a, u32 b) { return __byte_perm(a, b, 0x5410); }
__device__ __forceinline__ u32 lo2(u32 a, u32 b) { return __byte_perm(a, b, 0x7632); }

__device__ __forceinline__ void mma(float* c, u32 a0,u32 a1,u32 a2,u32 a3, u32 b0,u32 b1) {
    asm volatile("mma.sync.aligned.m16n8k16.row.col.f32.bf16.bf16.f32 "
        "{%0,%1,%2,%3},{%4,%5,%6,%7},{%8,%9},{%0,%1,%2,%3};"
        : "+f"(c[0]),"+f"(c[1]),"+f"(c[2]),"+f"(c[3])
        : "r"(a0),"r"(a1),"r"(a2),"r"(a3),"r"(b0),"r"(b1));
}
__device__ __forceinline__ int sw16(int r, int w) { return r*16 + (w ^ ((r&6)<<1)); }
__device__ __forceinline__ int sw32(int r, int w) { return r*32 + (w ^ ((r&7)<<2)); }

__device__ __forceinline__ void mma3(float* c, const u32* ah, const u32* al,
                                     u32 bh0, u32 bh1, u32 bl0, u32 bl1) {
    mma(c, ah[0],ah[1],ah[2],ah[3], bh0,bh1);
    mma(c, ah[0],ah[1],ah[2],ah[3], bl0,bl1);
    mma(c, al[0],al[1],al[2],al[3], bh0,bh1);
}

// ==================== kernel 0: split weights ====================
__global__ void __launch_bounds__(256) split_w(
    const float* __restrict__ Wq, const float* __restrict__ Wk,
    const float* __restrict__ Wv, const float* __restrict__ Wp)
{
    int t = blockIdx.x*256 + threadIdx.x;          // 65536
    int fo = t >> 8, f = t & 255;
    int src = ((fo>>5)*FF + f)*DD + (fo&31);       // W[h][f][d]
    g_w[t]          = splitpack(Wq[src]);
    g_w[65536 + t]  = splitpack(Wk[src]);
    g_w[131072 + t] = splitpack(Wv[src]);
    g_wp[t] = splitpack(Wp[t]);
}

// ==================== kernel 1: QKV ====================
// C[fout=256][t=64] = W^T x.  grid 768 = mat*256+nb, block 512 (16 warps).
// Warp w owns m-tile rows [16w,16w+16) x all 8 n-tiles.  acc[8][4].
__global__ void __launch_bounds__(512) qkv_kernel(const float* __restrict__ x)
{
    __shared__ u32 Ah[256*16], Al[256*16];
    __shared__ u32 Bh[64*16],  Bl[64*16];

    const int bid = blockIdx.x, nb = bid & 255, mat = bid >> 8;
    const int tid = threadIdx.x, wid = tid >> 5, lane = tid & 31;
    const u32* Wm = g_w + mat*65536;
    const float* xb = x + nb*(FF*TT);

    float acc[8][4];
    #pragma unroll
    for (int nt=0;nt<8;nt++) for (int p=0;p<4;p++) acc[nt][p]=0.f;

    for (int c = 0; c < 8; c++) {
        __syncthreads();
        #pragma unroll
        for (int m = 0; m < 4; m++) {        // stage A: 2048 uint4 / 512 thr
            int jj = tid + m*512, r = jj>>3, q = jj&7;
            uint4 p = *((const uint4*)(Wm + r*256 + c*32) + q);
            *(uint2*)&Ah[sw16(r,2*q)] = make_uint2(hi2(p.x,p.y), hi2(p.z,p.w));
            *(uint2*)&Al[sw16(r,2*q)] = make_uint2(lo2(p.x,p.y), lo2(p.z,p.w));
        }
        {   // stage B: transpose+split x; thread: t=tid>>3, 4 f's
            int t = tid>>3, q = tid&7;
            u32 sp[4];
            #pragma unroll
            for (int i = 0; i < 4; i++)
                sp[i] = splitpack(xb[(c*32 + q*4 + i)*TT + t]);
            Bh[sw16(t, q*2)]   = hi2(sp[0], sp[1]);
            Bh[sw16(t, q*2+1)] = hi2(sp[2], sp[3]);
            Bl[sw16(t, q*2)]   = lo2(sp[0], sp[1]);
            Bl[sw16(t, q*2+1)] = lo2(sp[2], sp[3]);
        }
        __syncthreads();

        #pragma unroll
        for (int kt = 0; kt < 2; kt++) {
            const int wq = kt*8 + (lane&3);
            const int r = wid*16 + (lane>>2);
            u32 ah[4], al[4];
            ah[0]=Ah[sw16(r,wq)];   ah[1]=Ah[sw16(r+8,wq)];
            ah[2]=Ah[sw16(r,wq+4)]; ah[3]=Ah[sw16(r+8,wq+4)];
            al[0]=Al[sw16(r,wq)];   al[1]=Al[sw16(r+8,wq)];
            al[2]=Al[sw16(r,wq+4)]; al[3]=Al[sw16(r+8,wq+4)];
            #pragma unroll
            for (int nt = 0; nt < 8; nt++) {
                int rb = nt*8 + (lane>>2);
                u32 bh0=Bh[sw16(rb,wq)], bh1=Bh[sw16(rb,wq+4)];
                u32 bl0=Bl[sw16(rb,wq)], bl1=Bl[sw16(rb,wq+4)];
                mma3(acc[nt], ah, al, bh0,bh1,bl0,bl1);
            }
        }
    }

    // epilogue: warp = 16-row fout strip; h = wid>>1, d0 = (wid&1)*16
    const int h = wid >> 1, d0 = (wid & 1) * 16;
    const float sc = (mat == 0) ? SCALE : 1.0f;
    if (mat < 2) {
        u32* dst = (mat ? g_k : g_q) + (h*NB + nb)*(TT*DD);
        int d = d0 + (lane>>2);
        #pragma unroll
        for (int nt = 0; nt < 8; nt++) {
            int t = nt*8 + 2*(lane&3);
            dst[t*32 + d]         = splitpack(acc[nt][0]*sc);
            dst[(t+1)*32 + d]     = splitpack(acc[nt][1]*sc);
            dst[t*32 + d + 8]     = splitpack(acc[nt][2]*sc);
            dst[(t+1)*32 + d + 8] = splitpack(acc[nt][3]*sc);
        }
    } else {
        u32* dst = g_v + (h*NB + nb)*(TT*DD);   // [d][s]
        int d = d0 + (lane>>2);
        #pragma unroll
        for (int nt = 0; nt < 8; nt++) {
            int s = nt*8 + 2*(lane&3);
            *(uint2*)&dst[d*64 + s] =
                make_uint2(splitpack(acc[nt][0]), splitpack(acc[nt][1]));
            *(uint2*)&dst[(d+8)*64 + s] =
                make_uint2(splitpack(acc[nt][2]), splitpack(acc[nt][3]));
        }
    }
}

// ==================== kernel 2: attention ====================
// grid 2048 = h*256 + j*32 + b, block 128 (warp = 16-row t-strip).
// K/V for agent i+1 prefetched into registers during compute of agent i.
__global__ void __launch_bounds__(128) attn_kernel()
{
    __shared__ u32 Qh[64*16], Ql[64*16];
    __shared__ u32 Kh[64*16], Kl[64*16];
    __shared__ u32 Vh[32*32], Vl[32*32];

    const int bid = blockIdx.x;
    const int b = bid & 31, j = (bid >> 5) & 7, h = bid >> 8;
    const int tid = threadIdx.x, wid = tid >> 5, lane = tid & 31;

    {   // stage Q once
        const uint4* qg = (const uint4*)(g_q + (h*NB + j*BB + b)*(TT*DD));
        #pragma unroll
        for (int m = 0; m < 4; m++) {
            int jj = tid + m*128, r = jj>>3, q = jj&7;
            uint4 p = qg[jj];
            *(uint2*)&Qh[sw16(r,2*q)] = make_uint2(hi2(p.x,p.y), hi2(p.z,p.w));
            *(uint2*)&Ql[sw16(r,2*q)] = make_uint2(lo2(p.x,p.y), lo2(p.z,p.w));
        }
    }

    const uint4* kbase = (const uint4*)(g_k + (h*NB + b)*(TT*DD));
    const uint4* vbase = (const uint4*)(g_v + (h*NB + b)*(TT*DD));
    const int kvstride = BB*TT*DD/4;          // uint4 per agent step

    float o[4][4];
    #pragma unroll
    for (int n=0;n<4;n++) for (int p=0;p<4;p++) o[n][p]=0.f;

    // prefetch agent 0
    uint4 kp[4], vp[4];
    #pragma unroll
    for (int m = 0; m < 4; m++) { kp[m] = kbase[tid + m*128]; vp[m] = vbase[tid + m*128]; }

    for (int i = 0; i < NA; i++) {
        __syncthreads();
        #pragma unroll
        for (int m = 0; m < 4; m++) {         // commit prefetched K/V to smem
            int jj = tid + m*128;
            { int r = jj>>3, q = jj&7; uint4 p = kp[m];
              *(uint2*)&Kh[sw16(r,2*q)] = make_uint2(hi2(p.x,p.y), hi2(p.z,p.w));
              *(uint2*)&Kl[sw16(r,2*q)] = make_uint2(lo2(p.x,p.y), lo2(p.z,p.w)); }
            { int r = jj>>4, q = jj&15; uint4 p = vp[m];
              *(uint2*)&Vh[sw32(r,2*q)] = make_uint2(hi2(p.x,p.y), hi2(p.z,p.w));
              *(uint2*)&Vl[sw32(r,2*q)] = make_uint2(lo2(p.x,p.y), lo2(p.z,p.w)); }
        }
        __syncthreads();

        if (i < NA-1) {   // prefetch next agent; hidden behind compute below
            const uint4* nk = kbase + (i+1)*kvstride;
            const uint4* nv = vbase + (i+1)*kvstride;
            #pragma unroll
            for (int m = 0; m < 4; m++) { kp[m] = nk[tid + m*128]; vp[m] = nv[tid + m*128]; }
        }

        // ---- S = Q K^T (t16 x s64) ----
        float s[8][4];
        #pragma unroll
        for (int n=0;n<8;n++) for (int p=0;p<4;p++) s[n][p]=0.f;

        u32 qh[2][4], ql[2][4];
        #pragma unroll
        for (int kt = 0; kt < 2; kt++) {
            int wq = kt*8 + (lane&3), r = wid*16 + (lane>>2);
            qh[kt][0]=Qh[sw16(r,wq)];   qh[kt][1]=Qh[sw16(r+8,wq)];
            qh[kt][2]=Qh[sw16(r,wq+4)]; qh[kt][3]=Qh[sw16(r+8,wq+4)];
            ql[kt][0]=Ql[sw16(r,wq)];   ql[kt][1]=Ql[sw16(r+8,wq)];
            ql[kt][2]=Ql[sw16(r,wq+4)]; ql[kt][3]=Ql[sw16(r+8,wq+4)];
        }
        #pragma unroll
        for (int nt = 0; nt < 8; nt++) {
            int rb = nt*8 + (lane>>2);
            #pragma unroll
            for (int kt = 0; kt < 2; kt++) {
                int wq = kt*8 + (lane&3);
                u32 bh0=Kh[sw16(rb,wq)], bh1=Kh[sw16(rb,wq+4)];
                u32 bl0=Kl[sw16(rb,wq)], bl1=Kl[sw16(rb,wq+4)];
                mma3(s[nt], qh[kt], ql[kt], bh0,bh1,bl0,bl1);
            }
        }

        // ---- softmax over s=64 ----
        float m0 = s[0][0], m1 = s[0][2];
        #pragma unroll
        for (int nt = 0; nt < 8; nt++) {
            m0 = fmaxf(m0, fmaxf(s[nt][0], s[nt][1]));
            m1 = fmaxf(m1, fmaxf(s[nt][2], s[nt][3]));
        }
        m0 = fmaxf(m0, __shfl_xor_sync(~0u, m0, 1)); m0 = fmaxf(m0, __shfl_xor_sync(~0u, m0, 2));
        m1 = fmaxf(m1, __shfl_xor_sync(~0u, m1, 1)); m1 = fmaxf(m1, __shfl_xor_sync(~0u, m1, 2));
        float sum0 = 0.f, sum1 = 0.f;
        #pragma unroll
        for (int nt = 0; nt < 8; nt++) {
            s[nt][0] = __expf(s[nt][0]-m0); s[nt][1] = __expf(s[nt][1]-m0);
            s[nt][2] = __expf(s[nt][2]-m1); s[nt][3] = __expf(s[nt][3]-m1);
            sum0 += s[nt][0] + s[nt][1];
            sum1 += s[nt][2] + s[nt][3];
        }
        sum0 += __shfl_xor_sync(~0u, sum0, 1); sum0 += __shfl_xor_sync(~0u, sum0, 2);
        sum1 += __shfl_xor_sync(~0u, sum1, 1); sum1 += __shfl_xor_sync(~0u, sum1, 2);
        float inv0 = __frcp_rn(sum0), inv1 = __frcp_rn(sum1);

        // ---- O += P V : P stays in registers as A-fragments ----
        #pragma unroll
        for (int kt = 0; kt < 4; kt++) {
            u32 x0, x1, ph[4], pl[4];
            x0 = splitpack(s[2*kt][0]*inv0);   x1 = splitpack(s[2*kt][1]*inv0);
            ph[0] = hi2(x0,x1); pl[0] = lo2(x0,x1);
            x0 = splitpack(s[2*kt][2]*inv1);   x1 = splitpack(s[2*kt][3]*inv1);
            ph[1] = hi2(x0,x1); pl[1] = lo2(x0,x1);
            x0 = splitpack(s[2*kt+1][0]*inv0); x1 = splitpack(s[2*kt+1][1]*inv0);
            ph[2] = hi2(x0,x1); pl[2] = lo2(x0,x1);
            x0 = splitpack(s[2*kt+1][2]*inv1); x1 = splitpack(s[2*kt+1][3]*inv1);
            ph[3] = hi2(x0,x1); pl[3] = lo2(x0,x1);
            #pragma unroll
            for (int nt = 0; nt < 4; nt++) {
                int rb = nt*8 + (lane>>2), wq = kt*8 + (lane&3);
                u32 bh0=Vh[sw32(rb,wq)], bh1=Vh[sw32(rb,wq+4)];
                u32 bl0=Vl[sw32(rb,wq)], bl1=Vl[sw32(rb,wq+4)];
                mma3(o[nt], ph, pl, bh0,bh1,bl0,bl1);
            }
        }
    }

    // epilogue: y[nb][t][h*32+d]
    const int nb = j*BB + b;
    const int t0 = wid*16 + (lane>>2);
    u32* yb = g_y + nb*(TT*FF) + h*32;
    #pragma unroll
    for (int nt = 0; nt < 4; nt++) {
        int d = nt*8 + 2*(lane&3);
        *(uint2*)&yb[t0*256 + d]     = make_uint2(splitpack(o[nt][0]), splitpack(o[nt][1]));
        *(uint2*)&yb[(t0+8)*256 + d] = make_uint2(splitpack(o[nt][2]), splitpack(o[nt][3]));
    }
}

// ==================== kernel 3: projection ====================
// C[t=64][g=256] = y Wp^T + bp.  grid 256 (nb), block 512 (16 warps).
// Warp: mt = wid&3 (16-row t-strip), nh = wid>>2 (64-g quarter = 8 n-tiles).
__global__ void __launch_bounds__(512) proj_kernel(
    const float* __restrict__ bp, float* __restrict__ out)
{
    __shared__ u32 Ah[64*16],  Al[64*16];
    __shared__ u32 Bh[256*16], Bl[256*16];

    const int nb = blockIdx.x;
    const int tid = threadIdx.x, wid = tid >> 5, lane = tid & 31;
    const int mt = wid & 3, nh = wid >> 2;

    float acc[8][4];
    #pragma unroll
    for (int n=0;n<8;n++) for (int p=0;p<4;p++) acc[n][p]=0.f;

    for (int c = 0; c < 8; c++) {
        __syncthreads();
        {   // stage A (y chunk): 512 uint4 / 512 thr
            int r = tid>>3, q = tid&7;
            uint4 p = *((const uint4*)(g_y + nb*(TT*FF) + r*256 + c*32) + q);
            *(uint2*)&Ah[sw16(r,2*q)] = make_uint2(hi2(p.x,p.y), hi2(p.z,p.w));
            *(uint2*)&Al[sw16(r,2*q)] = make_uint2(lo2(p.x,p.y), lo2(p.z,p.w));
        }
        #pragma unroll
        for (int m = 0; m < 4; m++) {    // stage B (Wp chunk): 2048 uint4
            int jj = tid + m*512, r = jj>>3, q = jj&7;
            uint4 p = *((const uint4*)(g_wp + r*256 + c*32) + q);
            *(uint2*)&Bh[sw16(r,2*q)] = make_uint2(hi2(p.x,p.y), hi2(p.z,p.w));
            *(uint2*)&Bl[sw16(r,2*q)] = make_uint2(lo2(p.x,p.y), lo2(p.z,p.w));
        }
        __syncthreads();

        #pragma unroll
        for (int kt = 0; kt < 2; kt++) {
            const int wq = kt*8 + (lane&3);
            const int r = mt*16 + (lane>>2);
            u32 ah[4], al[4];
            ah[0]=Ah[sw16(r,wq)];   ah[1]=Ah[sw16(r+8,wq)];
            ah[2]=Ah[sw16(r,wq+4)]; ah[3]=Ah[sw16(r+8,wq+4)];
            al[0]=Al[sw16(r,wq)];   al[1]=Al[sw16(r+8,wq)];
            al[2]=Al[sw16(r,wq+4)]; al[3]=Al[sw16(r+8,wq+4)];
            #pragma unroll
            for (int nt = 0; nt < 8; nt++) {
                int rb = nh*64 + nt*8 + (lane>>2);
                u32 bh0=Bh[sw16(rb,wq)], bh1=Bh[sw16(rb,wq+4)];
                u32 bl0=Bl[sw16(rb,wq)], bl1=Bl[sw16(rb,wq+4)];
                mma3(acc[nt], ah, al, bh0,bh1,bl0,bl1);
            }
        }
    }

    // epilogue: out[nb][g][t] + bp[g]
    const int t = mt*16 + (lane>>2);
    float* ob = out + nb*(FF*TT);
    #pragma unroll
    for (int nt = 0; nt < 8; nt++) {
        int g = nh*64 + nt*8 + 2*(lane&3);
        float b0 = __ldg(bp + g), b1 = __ldg(bp + g + 1);
        ob[g*64 + t]         = acc[nt][0] + b0;
        ob[(g+1)*64 + t]     = acc[nt][1] + b1;
        ob[g*64 + t + 8]     = acc[nt][2] + b0;
        ob[(g+1)*64 + t + 8] = acc[nt][3] + b1;
    }
}

// ==================== launch ====================
extern "C" void kernel_launch(void* const* d_in, const int* in_sizes, int n_in,
                              void* d_out, int out_size)
{
    (void)in_sizes; (void)n_in; (void)out_size;
    const float* x  = (const float*)d_in[0];
    const float* Wq = (const float*)d_in[1];
    const float* Wk = (const float*)d_in[2];
    const float* Wv = (const float*)d_in[3];
    const float* Wp = (const float*)d_in[4];
    const float* bp = (const float*)d_in[5];
    float* out = (float*)d_out;

    split_w<<<256, 256>>>(Wq, Wk, Wv, Wp);
    qkv_kernel<<<768, 512>>>(x);
    attn_kernel<<<2048, 128>>>();
    proj_kernel<<<256, 512>>>(bp, out);
}

// round 8
// speedup vs baseline: 1.1006x; 1.1006x over previous
#include <cuda_runtime.h>
#include <cuda_bf16.h>

#define NA 8
#define BB 32
#define NB 256
#define FF 256
#define TT 64
#define HH 8
#define DD 32
#define SCALE 0.0625f

typedef unsigned int u32;

// ---- packed (bf16 hi | bf16 lo<<16) intermediates ----
__device__ u32 g_w [3*FF*FF];      // [mat][fout=h*32+d][f]
__device__ u32 g_wp[FF*FF];        // [g][f]
__device__ u32 g_q [HH*NB*TT*DD];  // [h][nb][t][d]  (pre-scaled)
__device__ u32 g_k [HH*NB*TT*DD];  // [h][nb][s][d]
__device__ u32 g_v [HH*NB*DD*TT];  // [h][nb][d][s]
__device__ u32 g_y [NB*TT*FF];     // [nb][t][f]

__device__ __forceinline__ u32 splitpack(float x) {
    __nv_bfloat16 h = __float2bfloat16(x);
    __nv_bfloat16 l = __float2bfloat16(x - __bfloat162float(h));
    return (u32)__bfloat16_as_ushort(h) | ((u32)__bfloat16_as_ushort(l) << 16);
}
__device__ __forceinline__ u32 hi2(u32 a, u32 b) { return __byte_perm(a, b, 0x5410); }
__device__ __forceinline__ u32 lo2(u32 a, u32 b) { return __byte_perm(a, b, 0x7632); }

__device__ __forceinline__ void mma(float* c, u32 a0,u32 a1,u32 a2,u32 a3, u32 b0,u32 b1) {
    asm volatile("mma.sync.aligned.m16n8k16.row.col.f32.bf16.bf16.f32 "
        "{%0,%1,%2,%3},{%4,%5,%6,%7},{%8,%9},{%0,%1,%2,%3};"
        : "+f"(c[0]),"+f"(c[1]),"+f"(c[2]),"+f"(c[3])
        : "r"(a0),"r"(a1),"r"(a2),"r"(a3),"r"(b0),"r"(b1));
}
__device__ __forceinline__ int sw16(int r, int w) { return r*16 + (w ^ ((r&6)<<1)); }
__device__ __forceinline__ int sw32(int r, int w) { return r*32 + (w ^ ((r&7)<<2)); }

__device__ __forceinline__ void mma3(float* c, const u32* ah, const u32* al,
                                     u32 bh0, u32 bh1, u32 bl0, u32 bl1) {
    mma(c, ah[0],ah[1],ah[2],ah[3], bh0,bh1);
    mma(c, ah[0],ah[1],ah[2],ah[3], bl0,bl1);
    mma(c, al[0],al[1],al[2],al[3], bh0,bh1);
}

// ldmatrix x4 (non-trans)
__device__ __forceinline__ void ldsm4(u32& r0,u32& r1,u32& r2,u32& r3, const u32* p) {
    u32 a = (u32)__cvta_generic_to_shared(p);
    asm volatile("ldmatrix.sync.aligned.m8n8.x4.shared.b16 {%0,%1,%2,%3}, [%4];"
        : "=r"(r0),"=r"(r1),"=r"(r2),"=r"(r3) : "r"(a));
}
// A-fragment (m16k16) lane address pieces: R = base + (lane&7) + ((lane>>3)&1)*8,
// chunk = kt*8 + ((lane>>4)&1)*4.
// B-fragment pair (2 n-tiles): R = (ntp + (lane>>4))*8 + (lane&7),
// chunk = kt*8 + ((lane>>3)&1)*4.

// ==================== kernel 0: split weights ====================
__global__ void __launch_bounds__(256) split_w(
    const float* __restrict__ Wq, const float* __restrict__ Wk,
    const float* __restrict__ Wv, const float* __restrict__ Wp)
{
    int t = blockIdx.x*256 + threadIdx.x;          // 65536
    int fo = t >> 8, f = t & 255;
    int src = ((fo>>5)*FF + f)*DD + (fo&31);       // W[h][f][d]
    g_w[t]          = splitpack(Wq[src]);
    g_w[65536 + t]  = splitpack(Wk[src]);
    g_w[131072 + t] = splitpack(Wv[src]);
    g_wp[t] = splitpack(Wp[t]);
}

// ==================== kernel 1: QKV ====================
// C[fout=256][t=64] = W^T x.  grid 768 = mat*256+nb, block 512 (16 warps).
__global__ void __launch_bounds__(512) qkv_kernel(const float* __restrict__ x)
{
    __shared__ __align__(16) u32 Ah[256*16], Al[256*16];
    __shared__ __align__(16) u32 Bh[64*16],  Bl[64*16];

    const int bid = blockIdx.x, nb = bid & 255, mat = bid >> 8;
    const int tid = threadIdx.x, wid = tid >> 5, lane = tid & 31;
    const u32* Wm = g_w + mat*65536;
    const float* xb = x + nb*(FF*TT);

    const int aR = wid*16 + (lane&7) + ((lane>>3)&1)*8;
    const int aC = ((lane>>4)&1)*4;
    const int bRo = (lane>>4)*8 + (lane&7);
    const int bC = ((lane>>3)&1)*4;

    float acc[8][4];
    #pragma unroll
    for (int nt=0;nt<8;nt++) for (int p=0;p<4;p++) acc[nt][p]=0.f;

    for (int c = 0; c < 8; c++) {
        __syncthreads();
        #pragma unroll
        for (int m = 0; m < 4; m++) {        // stage A
            int jj = tid + m*512, r = jj>>3, q = jj&7;
            uint4 p = *((const uint4*)(Wm + r*256 + c*32) + q);
            *(uint2*)&Ah[sw16(r,2*q)] = make_uint2(hi2(p.x,p.y), hi2(p.z,p.w));
            *(uint2*)&Al[sw16(r,2*q)] = make_uint2(lo2(p.x,p.y), lo2(p.z,p.w));
        }
        {   // stage B: transpose+split x
            int t = tid>>3, q = tid&7;
            u32 sp[4];
            #pragma unroll
            for (int i = 0; i < 4; i++)
                sp[i] = splitpack(xb[(c*32 + q*4 + i)*TT + t]);
            Bh[sw16(t, q*2)]   = hi2(sp[0], sp[1]);
            Bh[sw16(t, q*2+1)] = hi2(sp[2], sp[3]);
            Bl[sw16(t, q*2)]   = lo2(sp[0], sp[1]);
            Bl[sw16(t, q*2+1)] = lo2(sp[2], sp[3]);
        }
        __syncthreads();

        #pragma unroll
        for (int kt = 0; kt < 2; kt++) {
            u32 ah[4], al[4];
            ldsm4(ah[0],ah[1],ah[2],ah[3], &Ah[sw16(aR, kt*8 + aC)]);
            ldsm4(al[0],al[1],al[2],al[3], &Al[sw16(aR, kt*8 + aC)]);
            #pragma unroll
            for (int ntp = 0; ntp < 8; ntp += 2) {
                u32 h0,h1,h2,h3, l0,l1,l2,l3;
                ldsm4(h0,h1,h2,h3, &Bh[sw16(ntp*8 + bRo, kt*8 + bC)]);
                ldsm4(l0,l1,l2,l3, &Bl[sw16(ntp*8 + bRo, kt*8 + bC)]);
                mma3(acc[ntp],   ah, al, h0,h1,l0,l1);
                mma3(acc[ntp+1], ah, al, h2,h3,l2,l3);
            }
        }
    }

    // epilogue: warp = 16-row fout strip; h = wid>>1, d0 = (wid&1)*16
    const int h = wid >> 1, d0 = (wid & 1) * 16;
    const float sc = (mat == 0) ? SCALE : 1.0f;
    if (mat < 2) {
        u32* dst = (mat ? g_k : g_q) + (h*NB + nb)*(TT*DD);
        int d = d0 + (lane>>2);
        #pragma unroll
        for (int nt = 0; nt < 8; nt++) {
            int t = nt*8 + 2*(lane&3);
            dst[t*32 + d]         = splitpack(acc[nt][0]*sc);
            dst[(t+1)*32 + d]     = splitpack(acc[nt][1]*sc);
            dst[t*32 + d + 8]     = splitpack(acc[nt][2]*sc);
            dst[(t+1)*32 + d + 8] = splitpack(acc[nt][3]*sc);
        }
    } else {
        u32* dst = g_v + (h*NB + nb)*(TT*DD);   // [d][s]
        int d = d0 + (lane>>2);
        #pragma unroll
        for (int nt = 0; nt < 8; nt++) {
            int s = nt*8 + 2*(lane&3);
            *(uint2*)&dst[d*64 + s] =
                make_uint2(splitpack(acc[nt][0]), splitpack(acc[nt][1]));
            *(uint2*)&dst[(d+8)*64 + s] =
                make_uint2(splitpack(acc[nt][2]), splitpack(acc[nt][3]));
        }
    }
}

// ==================== kernel 2: attention ====================
// grid 1024 = h*128 + jp*32 + b (jp = j-pair), block 256 (8 warps).
// Warp: jj = wid>>2 (which j of the pair), mt = wid&3 (16-row t-strip).
// K/V staged once per agent i serve both j's; prefetch into regs.
__global__ void __launch_bounds__(256) attn_kernel()
{
    __shared__ __align__(16) u32 Qh[128*16], Ql[128*16];   // 2 agents' Q
    __shared__ __align__(16) u32 Kh[64*16],  Kl[64*16];
    __shared__ __align__(16) u32 Vh[32*32],  Vl[32*32];

    const int bid = blockIdx.x;
    const int b = bid & 31, jp = (bid >> 5) & 3, h = bid >> 7;
    const int tid = threadIdx.x, wid = tid >> 5, lane = tid & 31;
    const int jj = wid >> 2, mt = wid & 3;

    {   // stage Q for both agents: 1024 uint4
        const uint4* qg = (const uint4*)(g_q + (h*NB + jp*2*BB + b)*(TT*DD));
        #pragma unroll
        for (int m = 0; m < 4; m++) {
            int idx = tid + m*256, rr = idx>>3, q = idx&7;
            uint4 p = qg[(rr>>6)*16384 + (rr&63)*8 + q];
            *(uint2*)&Qh[sw16(rr,2*q)] = make_uint2(hi2(p.x,p.y), hi2(p.z,p.w));
            *(uint2*)&Ql[sw16(rr,2*q)] = make_uint2(lo2(p.x,p.y), lo2(p.z,p.w));
        }
    }
    __syncthreads();

    // per-warp Q fragments (persistent)
    const int aR = jj*64 + mt*16 + (lane&7) + ((lane>>3)&1)*8;
    const int aC = ((lane>>4)&1)*4;
    const int bRo = (lane>>4)*8 + (lane&7);
    const int bC = ((lane>>3)&1)*4;
    u32 qh[2][4], ql[2][4];
    #pragma unroll
    for (int kt = 0; kt < 2; kt++) {
        ldsm4(qh[kt][0],qh[kt][1],qh[kt][2],qh[kt][3], &Qh[sw16(aR, kt*8 + aC)]);
        ldsm4(ql[kt][0],ql[kt][1],ql[kt][2],ql[kt][3], &Ql[sw16(aR, kt*8 + aC)]);
    }

    const uint4* kbase = (const uint4*)(g_k + (h*NB + b)*(TT*DD));
    const uint4* vbase = (const uint4*)(g_v + (h*NB + b)*(TT*DD));
    const int kvstride = BB*TT*DD/4;

    float o[4][4];
    #pragma unroll
    for (int n=0;n<4;n++) for (int p=0;p<4;p++) o[n][p]=0.f;

    uint4 kp[2], vp[2];
    #pragma unroll
    for (int m = 0; m < 2; m++) { kp[m] = kbase[tid + m*256]; vp[m] = vbase[tid + m*256]; }

    for (int i = 0; i < NA; i++) {
        __syncthreads();
        #pragma unroll
        for (int m = 0; m < 2; m++) {     // commit prefetched K/V
            int idx = tid + m*256;
            { int r = idx>>3, q = idx&7; uint4 p = kp[m];
              *(uint2*)&Kh[sw16(r,2*q)] = make_uint2(hi2(p.x,p.y), hi2(p.z,p.w));
              *(uint2*)&Kl[sw16(r,2*q)] = make_uint2(lo2(p.x,p.y), lo2(p.z,p.w)); }
            { int r = idx>>4, q = idx&15; uint4 p = vp[m];
              *(uint2*)&Vh[sw32(r,2*q)] = make_uint2(hi2(p.x,p.y), hi2(p.z,p.w));
              *(uint2*)&Vl[sw32(r,2*q)] = make_uint2(lo2(p.x,p.y), lo2(p.z,p.w)); }
        }
        __syncthreads();

        if (i < NA-1) {
            const uint4* nk = kbase + (i+1)*kvstride;
            const uint4* nv = vbase + (i+1)*kvstride;
            #pragma unroll
            for (int m = 0; m < 2; m++) { kp[m] = nk[tid + m*256]; vp[m] = nv[tid + m*256]; }
        }

        // ---- S = Q K^T (t16 x s64) ----
        float s[8][4];
        #pragma unroll
        for (int n=0;n<8;n++) for (int p=0;p<4;p++) s[n][p]=0.f;

        #pragma unroll
        for (int kt = 0; kt < 2; kt++) {
            #pragma unroll
            for (int ntp = 0; ntp < 8; ntp += 2) {
                u32 h0,h1,h2,h3, l0,l1,l2,l3;
                ldsm4(h0,h1,h2,h3, &Kh[sw16(ntp*8 + bRo, kt*8 + bC)]);
                ldsm4(l0,l1,l2,l3, &Kl[sw16(ntp*8 + bRo, kt*8 + bC)]);
                mma3(s[ntp],   qh[kt], ql[kt], h0,h1,l0,l1);
                mma3(s[ntp+1], qh[kt], ql[kt], h2,h3,l2,l3);
            }
        }

        // ---- softmax over s=64 ----
        float m0 = s[0][0], m1 = s[0][2];
        #pragma unroll
        for (int nt = 0; nt < 8; nt++) {
            m0 = fmaxf(m0, fmaxf(s[nt][0], s[nt][1]));
            m1 = fmaxf(m1, fmaxf(s[nt][2], s[nt][3]));
        }
        m0 = fmaxf(m0, __shfl_xor_sync(~0u, m0, 1)); m0 = fmaxf(m0, __shfl_xor_sync(~0u, m0, 2));
        m1 = fmaxf(m1, __shfl_xor_sync(~0u, m1, 1)); m1 = fmaxf(m1, __shfl_xor_sync(~0u, m1, 2));
        float sum0 = 0.f, sum1 = 0.f;
        #pragma unroll
        for (int nt = 0; nt < 8; nt++) {
            s[nt][0] = __expf(s[nt][0]-m0); s[nt][1] = __expf(s[nt][1]-m0);
            s[nt][2] = __expf(s[nt][2]-m1); s[nt][3] = __expf(s[nt][3]-m1);
            sum0 += s[nt][0] + s[nt][1];
            sum1 += s[nt][2] + s[nt][3];
        }
        sum0 += __shfl_xor_sync(~0u, sum0, 1); sum0 += __shfl_xor_sync(~0u, sum0, 2);
        sum1 += __shfl_xor_sync(~0u, sum1, 1); sum1 += __shfl_xor_sync(~0u, sum1, 2);
        float inv0 = __frcp_rn(sum0), inv1 = __frcp_rn(sum1);

        // ---- O += P V ----
        #pragma unroll
        for (int kt = 0; kt < 4; kt++) {
            u32 x0, x1, ph[4], pl[4];
            x0 = splitpack(s[2*kt][0]*inv0);   x1 = splitpack(s[2*kt][1]*inv0);
            ph[0] = hi2(x0,x1); pl[0] = lo2(x0,x1);
            x0 = splitpack(s[2*kt][2]*inv1);   x1 = splitpack(s[2*kt][3]*inv1);
            ph[1] = hi2(x0,x1); pl[1] = lo2(x0,x1);
            x0 = splitpack(s[2*kt+1][0]*inv0); x1 = splitpack(s[2*kt+1][1]*inv0);
            ph[2] = hi2(x0,x1); pl[2] = lo2(x0,x1);
            x0 = splitpack(s[2*kt+1][2]*inv1); x1 = splitpack(s[2*kt+1][3]*inv1);
            ph[3] = hi2(x0,x1); pl[3] = lo2(x0,x1);
            #pragma unroll
            for (int ntp = 0; ntp < 4; ntp += 2) {
                u32 h0,h1,h2,h3, l0,l1,l2,l3;
                ldsm4(h0,h1,h2,h3, &Vh[sw32(ntp*8 + bRo, kt*8 + bC)]);
                ldsm4(l0,l1,l2,l3, &Vl[sw32(ntp*8 + bRo, kt*8 + bC)]);
                mma3(o[ntp],   ph, pl, h0,h1,l0,l1);
                mma3(o[ntp+1], ph, pl, h2,h3,l2,l3);
            }
        }
    }

    // epilogue: y[nb][t][h*32+d]
    const int j = jp*2 + jj;
    const int nb = j*BB + b;
    const int t0 = mt*16 + (lane>>2);
    u32* yb = g_y + nb*(TT*FF) + h*32;
    #pragma unroll
    for (int nt = 0; nt < 4; nt++) {
        int d = nt*8 + 2*(lane&3);
        *(uint2*)&yb[t0*256 + d]     = make_uint2(splitpack(o[nt][0]), splitpack(o[nt][1]));
        *(uint2*)&yb[(t0+8)*256 + d] = make_uint2(splitpack(o[nt][2]), splitpack(o[nt][3]));
    }
}

// ==================== kernel 3: projection ====================
// C[t=64][g=256] = y Wp^T + bp.  grid 256 (nb), block 512 (16 warps).
__global__ void __launch_bounds__(512) proj_kernel(
    const float* __restrict__ bp, float* __restrict__ out)
{
    __shared__ __align__(16) u32 Ah[64*16],  Al[64*16];
    __shared__ __align__(16) u32 Bh[256*16], Bl[256*16];

    const int nb = blockIdx.x;
    const int tid = threadIdx.x, wid = tid >> 5, lane = tid & 31;
    const int mt = wid & 3, nh = wid >> 2;

    const int aR = mt*16 + (lane&7) + ((lane>>3)&1)*8;
    const int aC = ((lane>>4)&1)*4;
    const int bRo = (lane>>4)*8 + (lane&7);
    const int bC = ((lane>>3)&1)*4;

    float acc[8][4];
    #pragma unroll
    for (int n=0;n<8;n++) for (int p=0;p<4;p++) acc[n][p]=0.f;

    for (int c = 0; c < 8; c++) {
        __syncthreads();
        {   // stage A (y chunk)
            int r = tid>>3, q = tid&7;
            uint4 p = *((const uint4*)(g_y + nb*(TT*FF) + r*256 + c*32) + q);
            *(uint2*)&Ah[sw16(r,2*q)] = make_uint2(hi2(p.x,p.y), hi2(p.z,p.w));
            *(uint2*)&Al[sw16(r,2*q)] = make_uint2(lo2(p.x,p.y), lo2(p.z,p.w));
        }
        #pragma unroll
        for (int m = 0; m < 4; m++) {    // stage B (Wp chunk)
            int jj = tid + m*512, r = jj>>3, q = jj&7;
            uint4 p = *((const uint4*)(g_wp + r*256 + c*32) + q);
            *(uint2*)&Bh[sw16(r,2*q)] = make_uint2(hi2(p.x,p.y), hi2(p.z,p.w));
            *(uint2*)&Bl[sw16(r,2*q)] = make_uint2(lo2(p.x,p.y), lo2(p.z,p.w));
        }
        __syncthreads();

        #pragma unroll
        for (int kt = 0; kt < 2; kt++) {
            u32 ah[4], al[4];
            ldsm4(ah[0],ah[1],ah[2],ah[3], &Ah[sw16(aR, kt*8 + aC)]);
            ldsm4(al[0],al[1],al[2],al[3], &Al[sw16(aR, kt*8 + aC)]);
            #pragma unroll
            for (int ntp = 0; ntp < 8; ntp += 2) {
                u32 h0,h1,h2,h3, l0,l1,l2,l3;
                ldsm4(h0,h1,h2,h3, &Bh[sw16((nh*8 + ntp)*8 + bRo, kt*8 + bC)]);
                ldsm4(l0,l1,l2,l3, &Bl[sw16((nh*8 + ntp)*8 + bRo, kt*8 + bC)]);
                mma3(acc[ntp],   ah, al, h0,h1,l0,l1);
                mma3(acc[ntp+1], ah, al, h2,h3,l2,l3);
            }
        }
    }

    // epilogue: out[nb][g][t] + bp[g]
    const int t = mt*16 + (lane>>2);
    float* ob = out + nb*(FF*TT);
    #pragma unroll
    for (int nt = 0; nt < 8; nt++) {
        int g = nh*64 + nt*8 + 2*(lane&3);
        float b0 = __ldg(bp + g), b1 = __ldg(bp + g + 1);
        ob[g*64 + t]         = acc[nt][0] + b0;
        ob[(g+1)*64 + t]     = acc[nt][1] + b1;
        ob[g*64 + t + 8]     = acc[nt][2] + b0;
        ob[(g+1)*64 + t + 8] = acc[nt][3] + b1;
    }
}

// ==================== launch ====================
extern "C" void kernel_launch(void* const* d_in, const int* in_sizes, int n_in,
                              void* d_out, int out_size)
{
    (void)in_sizes; (void)n_in; (void)out_size;
    const float* x  = (const float*)d_in[0];
    const float* Wq = (const float*)d_in[1];
    const float* Wk = (const float*)d_in[2];
    const float* Wv = (const float*)d_in[3];
    const float* Wp = (const float*)d_in[4];
    const float* bp = (const float*)d_in[5];
    float* out = (float*)d_out;

    split_w<<<256, 256>>>(Wq, Wk, Wv, Wp);
    qkv_kernel<<<768, 512>>>(x);
    attn_kernel<<<1024, 256>>>();
    proj_kernel<<<256, 512>>>(bp, out);
}